// round 17
// baseline (speedup 1.0000x reference)
#include <cuda_runtime.h>
#include <math.h>

// Problem constants
#define B_    64
#define T_    50000
#define C_    4
#define MS_   4
#define D_    160
#define P_    25
#define L_    2000        // T_/P_

// Kernel 1 (frontend) config
#define TILE_T 2500
#define NT1    512
#define TILES_PER_B 20    // 50000/2500
#define XB_STRIDE (TILE_T + 32)   // halo 16 each side
#define S0_STRIDE (TILE_T + 8)    // halo 4 each side

// Kernel 2 (patch GEMM + LN) config
#define PB     80         // patches per block
#define NT2    224        // 200 active GEMM threads (10 patch-grp x 20 d-grp)
#define CHUNKS 25         // 2000/80
#define WP_STRIDE 164     // padded [k][d] row stride
#define XT_STRIDE 84      // padded [k][patch] row stride (16B-aligned rows)

// xs scratch: [b][m][t]  (51.2 MB, static device array — allocation-free)
__device__ float g_xs[(size_t)B_ * MS_ * T_];

__device__ __forceinline__ float gelu_f(float x) {
    return 0.5f * x * (1.0f + erff(x * 0.70710678118654752f));
}

// packed f32x2 helpers (sm_103a)
#define FMA_F32X2(acc, a, b) \
    asm("fma.rn.f32x2 %0, %1, %2, %0;" : "+l"(acc) : "l"(a), "l"(b))
#define DUP_F32X2(out, v) do {                                        \
    unsigned int _u = __float_as_uint(v);                             \
    asm("mov.b64 %0, {%1, %1};" : "=l"(out) : "r"(_u));               \
} while (0)
#define UNPACK_F32X2(lo, hi, in) do {                                 \
    unsigned int _a, _b;                                              \
    asm("mov.b64 {%0, %1}, %2;" : "=r"(_a), "=r"(_b) : "l"(in));      \
    lo = __uint_as_float(_a); hi = __uint_as_float(_b);               \
} while (0)

// ---------------------------------------------------------------------------
// K1: fused frontend. Stage B now 4 outputs/thread (float4 window loads).
// ---------------------------------------------------------------------------
__global__ __launch_bounds__(NT1, 2) void k_frontend(
    const float* __restrict__ X, const float* __restrict__ Mw,
    const float* __restrict__ w_env, const float* __restrict__ w_burst,
    const float* __restrict__ syn, const float* __restrict__ w_pre_dw,
    const float* __restrict__ w_pre_pw, float* __restrict__ m_patch)
{
    extern __shared__ char smem_raw[];
    float* xb  = (float*)smem_raw;                        // [4][XB_STRIDE]
    float* s0  = xb + 4 * XB_STRIDE;                      // [4][S0_STRIDE]
    unsigned char* mk = (unsigned char*)(s0 + 4 * S0_STRIDE); // [2500] pad 2512
    float* wenv  = (float*)(mk + 2512);
    float* wbur  = wenv + 100;
    float* wdw   = wbur + 36;
    float* pw    = wdw + 36;
    float* Wmc   = pw + 16;
    float* smtab = Wmc + 16;

    const int tid  = threadIdx.x;
    const int tile = blockIdx.x;
    const int b    = blockIdx.y;
    const int t0   = tile * TILE_T;

    if (tid < 100)                  wenv[tid]      = w_env[tid];
    if (tid >= 128 && tid < 164)    wbur[tid-128]  = w_burst[tid-128];
    if (tid >= 164 && tid < 200)    wdw[tid-164]   = w_pre_dw[tid-164];
    if (tid >= 200 && tid < 216)    pw[tid-200]    = w_pre_pw[tid-200];
    if (tid >= 216 && tid < 220) {
        int m = tid - 216;
        float w0 = log1pf(expf(syn[m*4+0]));
        float w1 = log1pf(expf(syn[m*4+1]));
        float w2 = log1pf(expf(syn[m*4+2]));
        float w3 = log1pf(expf(syn[m*4+3]));
        float inv = 1.0f / fmaxf(w0+w1+w2+w3, 1e-6f);
        Wmc[m*4+0] = w0*inv; Wmc[m*4+1] = w1*inv;
        Wmc[m*4+2] = w2*inv; Wmc[m*4+3] = w3*inv;
    }

    const float4* X4 = (const float4*)X;
    const float4* M4 = (const float4*)Mw;
    for (int i = tid; i < TILE_T + 32; i += NT1) {
        int gt = t0 - 16 + i;
        float4 v = make_float4(0.f, 0.f, 0.f, 0.f);
        if (gt >= 0 && gt < T_) {
            float4 xv = X4[b * T_ + gt];
            float4 mv = M4[b * T_ + gt];
            v.x = xv.x*mv.x; v.y = xv.y*mv.y; v.z = xv.z*mv.z; v.w = xv.w*mv.w;
            if (i >= 16 && i < 16 + TILE_T)
                mk[i-16] = (unsigned char)((mv.x > 0.f)       | ((mv.y > 0.f) << 1) |
                                           ((mv.z > 0.f) << 2)| ((mv.w > 0.f) << 3));
        }
        xb[0*XB_STRIDE + i] = v.x; xb[1*XB_STRIDE + i] = v.y;
        xb[2*XB_STRIDE + i] = v.z; xb[3*XB_STRIDE + i] = v.w;
    }
    __syncthreads();

    if (tid < 16) {
        int q = tid;
#pragma unroll
        for (int m = 0; m < 4; m++) {
            float s = 0.f;
#pragma unroll
            for (int c = 0; c < 4; c++) s += ((q >> c) & 1) ? Wmc[m*4+c] : 0.f;
            smtab[q*4 + m] = fminf(fmaxf(s, 0.f), 1.f);
        }
    }
    __syncthreads();

    // Stage B: 4 outputs/thread. j0 = 4*jb; output jj: global gS = t0+j0+jj-4.
    // Window xb[j0 .. j0+27] (28 floats = 7 float4, aligned: j0%4==0).
    // dx local i in [0,12): ad[i] = |x[j0+8+i]-x[j0+7+i]|, global t = t0+j0+i-8.
    for (int jb = tid; jb < (TILE_T + 8) / 4; jb += NT1) {
        const int j0  = jb * 4;
        const int gS0 = t0 + j0 - 4;
        bool okj[4];
#pragma unroll
        for (int jj = 0; jj < 4; jj++)
            okj[jj] = (gS0 + jj >= 0) && (gS0 + jj < T_);
        float a[4][4];
#pragma unroll
        for (int m = 0; m < 4; m++)
#pragma unroll
            for (int jj = 0; jj < 4; jj++) a[m][jj] = 0.f;

        if (okj[0] | okj[3]) {
            const bool interior = (t0 + j0 >= 9) && (t0 + j0 + 3 < T_);
#pragma unroll
            for (int c = 0; c < 4; c++) {
                const float* xc = xb + c * XB_STRIDE + j0;
                float xw[28];
#pragma unroll
                for (int i = 0; i < 7; i++) {
                    float4 v = *(const float4*)(xc + 4*i);
                    xw[4*i] = v.x; xw[4*i+1] = v.y; xw[4*i+2] = v.z; xw[4*i+3] = v.w;
                }
                float ad[12];
                if (interior) {
#pragma unroll
                    for (int i = 0; i < 12; i++)
                        ad[i] = fabsf(xw[8+i] - xw[7+i]);
                } else {
#pragma unroll
                    for (int i = 0; i < 12; i++) {
                        int gt = t0 + j0 + i - 8;
                        ad[i] = (gt >= 1 && gt < T_) ? fabsf(xw[8+i] - xw[7+i]) : 0.f;
                    }
                }
                const float ctr[4] = {xw[12], xw[13], xw[14], xw[15]};
#pragma unroll
                for (int i = 0; i < 28; i++) xw[i] = fabsf(xw[i]);
                float e[4] = {0.f, 0.f, 0.f, 0.f};
#pragma unroll
                for (int k = 0; k < 25; k++) {
                    float w = wenv[c*25+k];
                    e[0] += w * xw[k];   e[1] += w * xw[k+1];
                    e[2] += w * xw[k+2]; e[3] += w * xw[k+3];
                }
                float bu[4] = {0.f, 0.f, 0.f, 0.f};
#pragma unroll
                for (int k = 0; k < 9; k++) {
                    float w = wbur[c*9+k];
                    bu[0] += w * ad[k];   bu[1] += w * ad[k+1];
                    bu[2] += w * ad[k+2]; bu[3] += w * ad[k+3];
                }
#pragma unroll
                for (int jj = 0; jj < 4; jj++) {
                    float xm = 0.9f*e[jj] + 0.6f*bu[jj] + 0.2f*ctr[jj];
#pragma unroll
                    for (int m = 0; m < 4; m++) a[m][jj] += Wmc[m*4+c] * xm;
                }
            }
        }
#pragma unroll
        for (int m = 0; m < 4; m++)
#pragma unroll
            for (int jj = 0; jj < 4; jj++)
                s0[m*S0_STRIDE + j0 + jj] = okj[jj] ? a[m][jj] : 0.f;
    }
    __syncthreads();

    // Stage C: 4 outputs/thread; dwconv window [t, t+11] per m.
    for (int tb = tid; tb < TILE_T / 4; tb += NT1) {
        const int t = tb * 4;
        float s1[4][4];
#pragma unroll
        for (int m = 0; m < 4; m++) {
            const float* sm = s0 + m * S0_STRIDE + t;
            float4 v0 = *(const float4*)(sm);
            float4 v1 = *(const float4*)(sm + 4);
            float4 v2 = *(const float4*)(sm + 8);
            float sw[12] = {v0.x,v0.y,v0.z,v0.w, v1.x,v1.y,v1.z,v1.w,
                            v2.x,v2.y,v2.z,v2.w};
#pragma unroll
            for (int jj = 0; jj < 4; jj++) {
                float aa = 0.f;
#pragma unroll
                for (int k = 0; k < 9; k++) aa += wdw[m*9+k] * sw[jj+k];
                s1[m][jj] = gelu_f(aa);
            }
        }
        const uchar4 q4 = *(const uchar4*)(mk + t);
        const int qq[4] = {q4.x, q4.y, q4.z, q4.w};
#pragma unroll
        for (int o = 0; o < 4; o++) {
            float4 r;
            float* rp = (float*)&r;
#pragma unroll
            for (int jj = 0; jj < 4; jj++) {
                float aa = pw[o*4+0]*s1[0][jj] + pw[o*4+1]*s1[1][jj] +
                           pw[o*4+2]*s1[2][jj] + pw[o*4+3]*s1[3][jj];
                rp[jj] = gelu_f(aa) * smtab[qq[jj]*4 + o];
            }
            *(float4*)(g_xs + ((size_t)(b*4 + o)) * T_ + t0 + t) = r;
        }
    }

    for (int pl = tid; pl < TILE_T / P_; pl += NT1) {
        int cnt = 0;
#pragma unroll
        for (int p = 0; p < 25; p++) cnt += (mk[pl*25 + p] != 0);
        m_patch[b * L_ + tile * (TILE_T / P_) + pl] = (cnt > 2) ? 1.f : 0.f;
    }
}

// ---------------------------------------------------------------------------
// K2: patch projection GEMM (160 x 80patches, K=100) + LayerNorm(160).
// Software-pipelined k-loop: ping-pong prefetch of k+1's x/w LDS while
// computing k's 32 FFMA2 -> LDS latency hidden within a warp.
// ---------------------------------------------------------------------------
__global__ __launch_bounds__(NT2, 2) void k_gemm_ln(
    const float* __restrict__ w_proj, const float* __restrict__ gamma,
    const float* __restrict__ beta, float* __restrict__ out)
{
    extern __shared__ char smem_raw[];
    float* wp   = (float*)smem_raw;        // [100][WP_STRIDE]  65.6KB
    float* xt   = wp + 100 * WP_STRIDE;    // [100][XT_STRIDE]  33.6KB k-major
    float* red  = xt + 100 * XT_STRIDE;    // [80][20]          6.4KB
    float* mus  = red + PB * 20;           // [80]
    float* invs = mus + PB;                // [80]
    float* gs   = invs + PB;               // [160]
    float* bs   = gs + D_;                 // [160]

    const int tid   = threadIdx.x;
    const int chunk = blockIdx.x;
    const int b     = blockIdx.y;
    const int t0    = chunk * (PB * P_);

    // stage w_proj: global [d][m][p] -> smem [k][d], k = m*25+p
    for (int j = tid; j < D_ * 100; j += NT2) {
        int d = j / 100, k = j - d * 100;
        wp[k * WP_STRIDE + d] = w_proj[j];
    }
    // stage xs transposed: g_xs [m][t], t = l*25+p  ->  xt[(m*25+p)][l]
    for (int i = tid * 4; i < 4 * PB * P_; i += NT2 * 4) {
        int m = i / (PB * P_), t = i - m * (PB * P_);
        float4 v = *(const float4*)(g_xs + ((size_t)(b*4 + m)) * T_ + t0 + t);
        const float vv[4] = {v.x, v.y, v.z, v.w};
#pragma unroll
        for (int q = 0; q < 4; q++) {
            int tq = t + q;
            int l = tq / P_, p = tq - l * P_;
            xt[(m * 25 + p) * XT_STRIDE + l] = vv[q];
        }
    }
    if (tid < D_) { gs[tid] = gamma[tid]; bs[tid] = beta[tid]; }
    __syncthreads();

    // GEMM: 200 active threads, tid = pg*20 + dg; 8 d x 8 patches per thread
    const int pg = tid / 20, dg = tid % 20;
    const int d0 = dg * 8;
    const int l0 = pg * 8;
    const bool active = (tid < 200);

    unsigned long long acc2[4][8];   // [patch-pair j2][d i]
#pragma unroll
    for (int j = 0; j < 4; j++)
#pragma unroll
        for (int i = 0; i < 8; i++) acc2[j][i] = 0ULL;

    if (active) {
        ulonglong2 xA[2], xB[2];
        float4 wA[2], wB[2];
        // prologue: load k=0 into buffer 0
        xA[0] = *(const ulonglong2*)(xt + l0);
        xB[0] = *(const ulonglong2*)(xt + l0 + 4);
        wA[0] = *(const float4*)(wp + d0);
        wB[0] = *(const float4*)(wp + d0 + 4);
#pragma unroll 2
        for (int k = 0; k < 100; k++) {
            const int cur = k & 1, nxt = cur ^ 1;
            const int kn = (k < 99) ? (k + 1) : 99;
            // prefetch next iteration (hides LDS latency behind FFMA2 block)
            xA[nxt] = *(const ulonglong2*)(xt + kn * XT_STRIDE + l0);
            xB[nxt] = *(const ulonglong2*)(xt + kn * XT_STRIDE + l0 + 4);
            wA[nxt] = *(const float4*)(wp + kn * WP_STRIDE + d0);
            wB[nxt] = *(const float4*)(wp + kn * WP_STRIDE + d0 + 4);

            const unsigned long long xp[4] =
                {xA[cur].x, xA[cur].y, xB[cur].x, xB[cur].y};
            const float wv[8] = {wA[cur].x, wA[cur].y, wA[cur].z, wA[cur].w,
                                 wB[cur].x, wB[cur].y, wB[cur].z, wB[cur].w};
#pragma unroll
            for (int i = 0; i < 8; i++) {
                unsigned long long wd;
                DUP_F32X2(wd, wv[i]);
#pragma unroll
                for (int j = 0; j < 4; j++)
                    FMA_F32X2(acc2[j][i], xp[j], wd);
            }
        }
    }

    // unpack: acc[patch jj (0..7)][d i (0..7)]
    float acc[8][8];
#pragma unroll
    for (int j = 0; j < 4; j++)
#pragma unroll
        for (int i = 0; i < 8; i++)
            UNPACK_F32X2(acc[2*j][i], acc[2*j+1][i], acc2[j][i]);

    // pass 1: per-thread sums -> 20 partials per patch
    if (active) {
#pragma unroll
        for (int j = 0; j < 8; j++) {
            float s = 0.f;
#pragma unroll
            for (int i = 0; i < 8; i++) s += acc[j][i];
            red[(l0 + j) * 20 + dg] = s;
        }
    }
    __syncthreads();
    if (tid < PB) {
        float s = 0.f;
#pragma unroll
        for (int i = 0; i < 20; i++) s += red[tid * 20 + i];
        mus[tid] = s * (1.0f / 160.0f);
    }
    __syncthreads();
    // pass 2: centered sum of squares
    if (active) {
#pragma unroll
        for (int j = 0; j < 8; j++) {
            float mu = mus[l0 + j];
            float q = 0.f;
#pragma unroll
            for (int i = 0; i < 8; i++) { float d = acc[j][i] - mu; q += d * d; }
            red[(l0 + j) * 20 + dg] = q;
        }
    }
    __syncthreads();
    if (tid < PB) {
        float q = 0.f;
#pragma unroll
        for (int i = 0; i < 20; i++) q += red[tid * 20 + i];
        invs[tid] = rsqrtf(q * (1.0f / 160.0f) + 1e-5f);
    }
    __syncthreads();

    // normalize in registers, store straight to gmem (coalesced across dg)
    if (active) {
#pragma unroll
        for (int j = 0; j < 8; j++) {
            float mu = mus[l0 + j], iv = invs[l0 + j];
            size_t base = ((size_t)(b * L_) + chunk * PB + l0 + j) * D_ + d0;
            float4 o0, o1;
            o0.x = (acc[j][0]-mu)*iv*gs[d0+0] + bs[d0+0];
            o0.y = (acc[j][1]-mu)*iv*gs[d0+1] + bs[d0+1];
            o0.z = (acc[j][2]-mu)*iv*gs[d0+2] + bs[d0+2];
            o0.w = (acc[j][3]-mu)*iv*gs[d0+3] + bs[d0+3];
            o1.x = (acc[j][4]-mu)*iv*gs[d0+4] + bs[d0+4];
            o1.y = (acc[j][5]-mu)*iv*gs[d0+5] + bs[d0+5];
            o1.z = (acc[j][6]-mu)*iv*gs[d0+6] + bs[d0+6];
            o1.w = (acc[j][7]-mu)*iv*gs[d0+7] + bs[d0+7];
            *(float4*)(out + base)     = o0;
            *(float4*)(out + base + 4) = o1;
        }
    }
}

// ---------------------------------------------------------------------------
extern "C" void kernel_launch(void* const* d_in, const int* in_sizes, int n_in,
                              void* d_out, int out_size)
{
    (void)in_sizes; (void)n_in; (void)out_size;
    const float* X        = (const float*)d_in[0];
    const float* Mw       = (const float*)d_in[1];
    const float* w_env    = (const float*)d_in[2];
    const float* w_burst  = (const float*)d_in[3];
    const float* syn      = (const float*)d_in[4];
    const float* w_pre_dw = (const float*)d_in[5];
    const float* w_pre_pw = (const float*)d_in[6];
    const float* w_proj   = (const float*)d_in[7];
    const float* gamma    = (const float*)d_in[8];
    const float* beta     = (const float*)d_in[9];

    float* out     = (float*)d_out;
    float* m_patch = out + (size_t)B_ * L_ * D_;   // h first, then m_patch

    const size_t smem1 = (4 * XB_STRIDE + 4 * S0_STRIDE) * sizeof(float)
                         + 2512 + 268 * sizeof(float);
    const size_t smem2 = (100 * WP_STRIDE + 100 * XT_STRIDE + PB * 20 + 2 * PB
                          + 2 * D_) * sizeof(float);

    cudaFuncSetAttribute(k_frontend, cudaFuncAttributeMaxDynamicSharedMemorySize,
                         (int)smem1);
    cudaFuncSetAttribute(k_gemm_ln, cudaFuncAttributeMaxDynamicSharedMemorySize,
                         (int)smem2);

    dim3 g1(TILES_PER_B, B_);
    dim3 g2(CHUNKS, B_);
    k_frontend<<<g1, NT1, smem1>>>(X, Mw, w_env, w_burst, syn,
                                   w_pre_dw, w_pre_pw, m_patch);
    k_gemm_ln<<<g2, NT2, smem2>>>(w_proj, gamma, beta, out);
}